// round 3
// baseline (speedup 1.0000x reference)
#include <cuda_runtime.h>
#include <cuda_bf16.h>
#include <cstdint>

// ---------------------------------------------------------------------------
// MultiLevelFeatureSampler on GB300 (sm_103a via base-target sm_103 SASS)
//
// Per point (b, nn): D[128x256] = P[128x83] @ W^T (+ bias).  P = gather of 83
// patch taps (7x7/5x5/3x3 over 3 levels), tap index set shared across the 128
// channels.  Output block per point is contiguous (torch .view scramble).
//
// fp32 via split-bf16: a = ah+al; D = Ah*Bh + Ah*Bl + Al*Bh (fp32 accum)
// using mma.sync m16n8k16 bf16 HMMA (tcgen05 unavailable: harness PTX target
// is sm_103 without the 'a' feature suffix).
// W is converted to (Bh,Bl) ONCE by a prologue kernel into __device__ scratch
// laid out exactly as the smem tile; CTAs pull it via cp.async overlapped
// with the gather.
// ---------------------------------------------------------------------------

#define BSZ   4
#define NPTS  512
#define CCH   128
#define DTOT  83
#define KPAD  96          // 6 k-steps of 16
#define STRD  104         // row stride in bf16 elems (208 B, ldmatrix conflict-free)
#define NOUT  256

#define H0 93
#define W0 305
#define H1 47
#define W1 153
#define H2 24
#define W2 77

// ---- smem layout (bytes) ----
#define OFF_DBASE   0                         // 83 * 8B tap base pointers
#define OFF_DSTRIDE 672                       // 83 * 4B channel strides
#define OFF_BIAS    1024                      // 256 * 4B
#define OFF_AH      2048                      // 128 x 104 bf16 = 26624
#define OFF_AL      (OFF_AH + CCH * STRD * 2)     // 28672
#define OFF_BH      (OFF_AL + CCH * STRD * 2)     // 55296  (256 x 104 bf16)
#define OFF_BL      (OFF_BH + NOUT * STRD * 2)    // 108544
#define SMEM_TOTAL  (OFF_BL + NOUT * STRD * 2)    // 161792 (~158 KB)

// W split-bf16 scratch, [0]=hi, [1]=lo, each row-major 256 x STRD (pads zeroed)
__device__ __align__(16) __nv_bfloat16 g_B[2][NOUT * STRD];

// ---------------------------------------------------------------------------
__device__ __forceinline__ uint32_t smem_u32(const void* p) {
    uint32_t a;
    asm("{ .reg .u64 t; cvta.to.shared.u64 t, %1; cvt.u32.u64 %0, t; }"
        : "=r"(a) : "l"(p));
    return a;
}

__device__ __forceinline__ void cp16(uint32_t dst, const void* src) {
    asm volatile("cp.async.cg.shared.global [%0], [%1], 16;"
                 :: "r"(dst), "l"(src) : "memory");
}

__device__ __forceinline__ void ldsm4(uint32_t* r, uint32_t addr) {
    asm volatile("ldmatrix.sync.aligned.m8n8.x4.shared.b16 {%0,%1,%2,%3}, [%4];"
                 : "=r"(r[0]), "=r"(r[1]), "=r"(r[2]), "=r"(r[3]) : "r"(addr));
}

__device__ __forceinline__ void hmma(float* c, const uint32_t* a, const uint32_t* b) {
    asm volatile(
        "mma.sync.aligned.m16n8k16.row.col.f32.bf16.bf16.f32 "
        "{%0,%1,%2,%3}, {%4,%5,%6,%7}, {%8,%9}, {%0,%1,%2,%3};"
        : "+f"(c[0]), "+f"(c[1]), "+f"(c[2]), "+f"(c[3])
        : "r"(a[0]), "r"(a[1]), "r"(a[2]), "r"(a[3]), "r"(b[0]), "r"(b[1]));
}

// ---------------------------------------------------------------------------
// Prologue: W (256x83 fp32) -> g_B hi/lo bf16, row stride STRD, pads zeroed.
__global__ void prep_B_kernel(const float* __restrict__ Wg) {
    int idx = blockIdx.x * 256 + threadIdx.x;
    if (idx >= NOUT * STRD) return;
    int row = idx / STRD;
    int col = idx - row * STRD;
    float v = (col < DTOT) ? Wg[row * DTOT + col] : 0.f;
    __nv_bfloat16 hi = __float2bfloat16(v);
    __nv_bfloat16 lo = __float2bfloat16(v - __bfloat162float(hi));
    g_B[0][idx] = hi;
    g_B[1][idx] = lo;
}

// ---------------------------------------------------------------------------
__global__ void __launch_bounds__(256, 1)
mlfs_kernel(const float* __restrict__ points,
            const float* __restrict__ feat0,
            const float* __restrict__ feat1,
            const float* __restrict__ feat2,
            const float* __restrict__ biasg,
            float* __restrict__ out) {
    extern __shared__ char smem[];
    const uint32_t smem_base = smem_u32(smem);
    const int tid = threadIdx.x;
    const int wid = tid >> 5;
    const int lane = tid & 31;

    const int bi = blockIdx.x >> 9;     // batch
    const int nn = blockIdx.x & 511;    // point

    // ---- phase 0: B copy (async), bias, tap table, A-pad zero ----
    {   // pull Bh|Bl (contiguous 106496 B) from global scratch
        const char* src = (const char*)g_B;
        uint32_t dst = smem_base + OFF_BH;
        #pragma unroll 2
        for (int i = tid; i < (2 * NOUT * STRD * 2) / 16; i += 256)
            cp16(dst + i * 16, src + (size_t)i * 16);
        asm volatile("cp.async.commit_group;" ::: "memory");
    }
    if (tid < 64)
        ((float4*)(smem + OFF_BIAS))[tid] = ((const float4*)biasg)[tid];

    if (tid < DTOT) {
        int d = tid;
        const float* f; int H, Wd, ks, dd;
        if (d < 49)      { f = feat0; H = H0; Wd = W0; ks = 7; dd = d; }
        else if (d < 74) { f = feat1; H = H1; Wd = W1; ks = 5; dd = d - 49; }
        else             { f = feat2; H = H2; Wd = W2; ks = 3; dd = d - 74; }
        int half = ks >> 1;
        int jj = dd / ks - half;   // row (y) offset
        int kk = dd % ks - half;   // col (x) offset
        float px = points[(bi * NPTS + nn) * 2 + 0];
        float py = points[(bi * NPTS + nn) * 2 + 1];
        float x = fminf(fmaxf(px * (float)(Wd - 1), 0.f), (float)(Wd - 1));
        float y = fminf(fmaxf(py * (float)(H  - 1), 0.f), (float)(H  - 1));
        int ox = (int)floorf(fminf(fmaxf(x + (float)kk, 0.f), (float)(Wd - 1)));
        int oy = (int)floorf(fminf(fmaxf(y + (float)jj, 0.f), (float)(H  - 1)));
        *(int*)(smem + OFF_DSTRIDE + d * 4) = H * Wd;
        *(const float**)(smem + OFF_DBASE + d * 8) =
            f + (size_t)bi * CCH * H * Wd + (oy * Wd + ox);
    }

    // zero A pad cols 80..103 (gather rewrites 80..82): tid<256 covers
    // 2 matrices x 128 rows
    {
        int mrow = tid & 127;
        char* base = smem + ((tid & 128) ? OFF_AL : OFF_AH) + mrow * 208 + 160;
        float4 z = make_float4(0.f, 0.f, 0.f, 0.f);
        ((float4*)base)[0] = z; ((float4*)base)[1] = z; ((float4*)base)[2] = z;
    }
    __syncthreads();

    // ---- phase 1: gather + split-convert A (128 x 83) ----
    {
        char* ah = smem + OFF_AH;
        char* al = smem + OFF_AL;
        for (int e = tid; e < CCH * DTOT; e += 256) {
            int c = e / DTOT;
            int d = e - c * DTOT;
            const float* bp = *(const float* const*)(smem + OFF_DBASE + d * 8);
            int st = *(const int*)(smem + OFF_DSTRIDE + d * 4);
            float v = __ldg(bp + (size_t)c * st);
            __nv_bfloat16 hi = __float2bfloat16(v);
            __nv_bfloat16 lo = __float2bfloat16(v - __bfloat162float(hi));
            int sw = c * 208 + d * 2;
            *(__nv_bfloat16*)(ah + sw) = hi;
            *(__nv_bfloat16*)(al + sw) = lo;
        }
    }
    asm volatile("cp.async.wait_group 0;" ::: "memory");
    __syncthreads();

    // ---- phase 2: MMA.  warps 2(M) x 4(N), warp tile 64x64 ----
    const int wm = wid >> 2;
    const int wn = wid & 3;
    float acc[4][8][4];
    #pragma unroll
    for (int mt = 0; mt < 4; ++mt)
        #pragma unroll
        for (int nt = 0; nt < 8; ++nt)
            #pragma unroll
            for (int q = 0; q < 4; ++q) acc[mt][nt][q] = 0.f;

    const uint32_t lrow = lane & 15;
    const uint32_t kof2 = ((lane >> 4) << 3) * 2;  // byte offset 0 or 16

    #pragma unroll
    for (int pass = 0; pass < 3; ++pass) {
        uint32_t Abase = smem_base + ((pass == 2) ? OFF_AL : OFF_AH);
        uint32_t Bbase = smem_base + ((pass == 1) ? OFF_BL : OFF_BH);
        uint32_t aAddr0 = Abase + (wm * 64 + lrow) * 208 + kof2;
        uint32_t bAddr0 = Bbase + (wn * 64 + lrow) * 208 + kof2;
        #pragma unroll
        for (int ks = 0; ks < KPAD / 16; ++ks) {
            uint32_t a[4][4], b[8][2], t[4];
            #pragma unroll
            for (int mt = 0; mt < 4; ++mt)
                ldsm4(a[mt], aAddr0 + mt * 16 * 208 + ks * 32);
            #pragma unroll
            for (int np = 0; np < 4; ++np) {
                ldsm4(t, bAddr0 + np * 16 * 208 + ks * 32);
                b[2 * np + 0][0] = t[0]; b[2 * np + 1][0] = t[1];
                b[2 * np + 0][1] = t[2]; b[2 * np + 1][1] = t[3];
            }
            #pragma unroll
            for (int mt = 0; mt < 4; ++mt)
                #pragma unroll
                for (int nt = 0; nt < 8; ++nt)
                    hmma(acc[mt][nt], a[mt], b[nt]);
        }
    }

    // ---- phase 3: epilogue (bias + direct coalesced-enough STG) ----
    {
        const float* bs = (const float*)(smem + OFF_BIAS);
        float* outp = out + (size_t)(bi * NPTS + nn) * (CCH * NOUT);
        const int r0 = wm * 64 + (lane >> 2);
        const int c0 = wn * 64 + 2 * (lane & 3);
        float2 bv[8];
        #pragma unroll
        for (int nt = 0; nt < 8; ++nt)
            bv[nt] = *(const float2*)(bs + c0 + nt * 8);
        #pragma unroll
        for (int mt = 0; mt < 4; ++mt) {
            const int row = r0 + mt * 16;
            #pragma unroll
            for (int nt = 0; nt < 8; ++nt) {
                const int col = c0 + nt * 8;
                float2 v0, v1;
                v0.x = acc[mt][nt][0] + bv[nt].x;
                v0.y = acc[mt][nt][1] + bv[nt].y;
                v1.x = acc[mt][nt][2] + bv[nt].x;
                v1.y = acc[mt][nt][3] + bv[nt].y;
                *(float2*)(outp + (size_t)row * NOUT + col) = v0;
                *(float2*)(outp + (size_t)(row + 8) * NOUT + col) = v1;
            }
        }
    }
}

// ---------------------------------------------------------------------------
extern "C" void kernel_launch(void* const* d_in, const int* in_sizes, int n_in,
                              void* d_out, int out_size) {
    const float* points = (const float*)d_in[0];
    const float* feat0  = (const float*)d_in[1];
    const float* feat1  = (const float*)d_in[2];
    const float* feat2  = (const float*)d_in[3];
    const float* Wg     = (const float*)d_in[4];
    const float* biasg  = (const float*)d_in[5];
    float* out = (float*)d_out;

    prep_B_kernel<<<(NOUT * STRD + 255) / 256, 256>>>(Wg);

    cudaFuncSetAttribute(mlfs_kernel,
                         cudaFuncAttributeMaxDynamicSharedMemorySize, SMEM_TOTAL);
    mlfs_kernel<<<BSZ * NPTS, 256, SMEM_TOTAL>>>(points, feat0, feat1, feat2,
                                                 biasg, out);
}

// round 4
// speedup vs baseline: 1.0656x; 1.0656x over previous
#include <cuda_runtime.h>
#include <cuda_bf16.h>
#include <cstdint>

// ---------------------------------------------------------------------------
// MultiLevelFeatureSampler on GB300 (sm_103a via base-target sm_103 SASS)
//
// Per point (b, nn): D[128x256] = P[128x83] @ W^T (+ bias).  P = gather of 83
// patch taps (7x7/5x5/3x3 over 3 levels), tap index set shared across the 128
// channels.  Output block per point is contiguous (torch .view scramble).
//
// fp32 via split-bf16: a = ah+al; D = Ah*Bh + Ah*Bl + Al*Bh (fp32 accum)
// using mma.sync m16n8k16 bf16 HMMA.
//
// R4: N-split across 2 CTAs per point (grid 4096).  smem ~105KB -> 2 CTAs/SM,
// acc regs halved (64) -> no spill, 16 warps/SM hide the serial phase chain.
// ---------------------------------------------------------------------------

#define BSZ   4
#define NPTS  512
#define CCH   128
#define DTOT  83
#define KPAD  96          // 6 k-steps of 16
#define STRD  104         // row stride in bf16 elems (208 B, ldmatrix conflict-free)
#define NOUT  256
#define NHALF 128         // per-CTA output columns

#define H0 93
#define W0 305
#define H1 47
#define W1 153
#define H2 24
#define W2 77

// ---- smem layout (bytes) ----
#define OFF_DBASE   0                             // 83 * 8B tap base pointers
#define OFF_DSTRIDE 672                           // 83 * 4B channel strides
#define OFF_BIAS    1008                          // 128 * 4B (this CTA's half)
#define OFF_AH      1536                          // 128 x 104 bf16 = 26624
#define OFF_AL      (OFF_AH + CCH * STRD * 2)     // 28160
#define OFF_BH      (OFF_AL + CCH * STRD * 2)     // 54784 (128 x 104 bf16)
#define OFF_BL      (OFF_BH + NHALF * STRD * 2)   // 81408
#define SMEM_TOTAL  (OFF_BL + NHALF * STRD * 2)   // 108032 (~105.5 KB)

// W split-bf16 scratch, [0]=hi, [1]=lo, each row-major 256 x STRD (pads zeroed)
__device__ __align__(16) __nv_bfloat16 g_B[2][NOUT * STRD];

// ---------------------------------------------------------------------------
__device__ __forceinline__ uint32_t smem_u32(const void* p) {
    uint32_t a;
    asm("{ .reg .u64 t; cvta.to.shared.u64 t, %1; cvt.u32.u64 %0, t; }"
        : "=r"(a) : "l"(p));
    return a;
}

__device__ __forceinline__ void cp16(uint32_t dst, const void* src) {
    asm volatile("cp.async.cg.shared.global [%0], [%1], 16;"
                 :: "r"(dst), "l"(src) : "memory");
}

__device__ __forceinline__ void ldsm4(uint32_t* r, uint32_t addr) {
    asm volatile("ldmatrix.sync.aligned.m8n8.x4.shared.b16 {%0,%1,%2,%3}, [%4];"
                 : "=r"(r[0]), "=r"(r[1]), "=r"(r[2]), "=r"(r[3]) : "r"(addr));
}

__device__ __forceinline__ void hmma(float* c, const uint32_t* a, const uint32_t* b) {
    asm volatile(
        "mma.sync.aligned.m16n8k16.row.col.f32.bf16.bf16.f32 "
        "{%0,%1,%2,%3}, {%4,%5,%6,%7}, {%8,%9}, {%0,%1,%2,%3};"
        : "+f"(c[0]), "+f"(c[1]), "+f"(c[2]), "+f"(c[3])
        : "r"(a[0]), "r"(a[1]), "r"(a[2]), "r"(a[3]), "r"(b[0]), "r"(b[1]));
}

// ---------------------------------------------------------------------------
// Prologue: W (256x83 fp32) -> g_B hi/lo bf16, row stride STRD, pads zeroed.
__global__ void prep_B_kernel(const float* __restrict__ Wg) {
    int idx = blockIdx.x * 256 + threadIdx.x;
    if (idx >= NOUT * STRD) return;
    int row = idx / STRD;
    int col = idx - row * STRD;
    float v = (col < DTOT) ? Wg[row * DTOT + col] : 0.f;
    __nv_bfloat16 hi = __float2bfloat16(v);
    __nv_bfloat16 lo = __float2bfloat16(v - __bfloat162float(hi));
    g_B[0][idx] = hi;
    g_B[1][idx] = lo;
}

// ---------------------------------------------------------------------------
__global__ void __launch_bounds__(256, 2)
mlfs_kernel(const float* __restrict__ points,
            const float* __restrict__ feat0,
            const float* __restrict__ feat1,
            const float* __restrict__ feat2,
            const float* __restrict__ biasg,
            float* __restrict__ out) {
    extern __shared__ char smem[];
    const uint32_t smem_base = smem_u32(smem);
    const int tid = threadIdx.x;
    const int wid = tid >> 5;
    const int lane = tid & 31;

    const int pt = blockIdx.x >> 1;     // global point id (b*512 + nn)
    const int hh = blockIdx.x & 1;      // N half
    const int bi = pt >> 9;             // batch
    const int nn = pt & 511;            // point within batch

    // ---- phase 0: B-half copy (async), bias, tap table, A-pad zero ----
    {   // Bh half then Bl half, each 128 rows x 208B contiguous in g_B
        const char* srcH = (const char*)(g_B[0] + hh * NHALF * STRD);
        const char* srcL = (const char*)(g_B[1] + hh * NHALF * STRD);
        const int n16 = (NHALF * STRD * 2) / 16;   // 1664 per matrix
        uint32_t dstH = smem_base + OFF_BH;
        uint32_t dstL = smem_base + OFF_BL;
        #pragma unroll 2
        for (int i = tid; i < n16; i += 256) {
            cp16(dstH + i * 16, srcH + (size_t)i * 16);
            cp16(dstL + i * 16, srcL + (size_t)i * 16);
        }
        asm volatile("cp.async.commit_group;" ::: "memory");
    }
    if (tid < 32)
        ((float4*)(smem + OFF_BIAS))[tid] =
            ((const float4*)(biasg + hh * NHALF))[tid];

    if (tid < DTOT) {
        int d = tid;
        const float* f; int H, Wd, ks, dd;
        if (d < 49)      { f = feat0; H = H0; Wd = W0; ks = 7; dd = d; }
        else if (d < 74) { f = feat1; H = H1; Wd = W1; ks = 5; dd = d - 49; }
        else             { f = feat2; H = H2; Wd = W2; ks = 3; dd = d - 74; }
        int half = ks >> 1;
        int jj = dd / ks - half;   // row (y) offset
        int kk = dd % ks - half;   // col (x) offset
        float px = points[pt * 2 + 0];
        float py = points[pt * 2 + 1];
        float x = fminf(fmaxf(px * (float)(Wd - 1), 0.f), (float)(Wd - 1));
        float y = fminf(fmaxf(py * (float)(H  - 1), 0.f), (float)(H  - 1));
        int ox = (int)floorf(fminf(fmaxf(x + (float)kk, 0.f), (float)(Wd - 1)));
        int oy = (int)floorf(fminf(fmaxf(y + (float)jj, 0.f), (float)(H  - 1)));
        *(int*)(smem + OFF_DSTRIDE + d * 4) = H * Wd;
        *(const float**)(smem + OFF_DBASE + d * 8) =
            f + (size_t)bi * CCH * H * Wd + (oy * Wd + ox);
    }

    // zero A pad cols 80..103 (gather rewrites 80..82): 256 threads cover
    // 2 matrices x 128 rows
    {
        int mrow = tid & 127;
        char* base = smem + ((tid & 128) ? OFF_AL : OFF_AH) + mrow * 208 + 160;
        float4 z = make_float4(0.f, 0.f, 0.f, 0.f);
        ((float4*)base)[0] = z; ((float4*)base)[1] = z; ((float4*)base)[2] = z;
    }
    __syncthreads();

    // ---- phase 1: gather + split-convert A (128 x 83) ----
    {
        char* ah = smem + OFF_AH;
        char* al = smem + OFF_AL;
        for (int e = tid; e < CCH * DTOT; e += 256) {
            int c = e / DTOT;
            int d = e - c * DTOT;
            const float* bp = *(const float* const*)(smem + OFF_DBASE + d * 8);
            int st = *(const int*)(smem + OFF_DSTRIDE + d * 4);
            float v = __ldg(bp + (size_t)c * st);
            __nv_bfloat16 hi = __float2bfloat16(v);
            __nv_bfloat16 lo = __float2bfloat16(v - __bfloat162float(hi));
            int sw = c * 208 + d * 2;
            *(__nv_bfloat16*)(ah + sw) = hi;
            *(__nv_bfloat16*)(al + sw) = lo;
        }
    }
    asm volatile("cp.async.wait_group 0;" ::: "memory");
    __syncthreads();

    // ---- phase 2: MMA.  warps 2(M) x 4(N), warp tile 64x32 ----
    const int wm = wid >> 2;
    const int wn = wid & 3;
    float acc[4][4][4];
    #pragma unroll
    for (int mt = 0; mt < 4; ++mt)
        #pragma unroll
        for (int nt = 0; nt < 4; ++nt)
            #pragma unroll
            for (int q = 0; q < 4; ++q) acc[mt][nt][q] = 0.f;

    const uint32_t lrow = lane & 15;
    const uint32_t kof2 = ((lane >> 4) << 3) * 2;  // byte offset 0 or 16

    #pragma unroll
    for (int pass = 0; pass < 3; ++pass) {
        uint32_t Abase = smem_base + ((pass == 2) ? OFF_AL : OFF_AH);
        uint32_t Bbase = smem_base + ((pass == 1) ? OFF_BL : OFF_BH);
        uint32_t aAddr0 = Abase + (wm * 64 + lrow) * 208 + kof2;
        uint32_t bAddr0 = Bbase + (wn * 32 + lrow) * 208 + kof2;
        #pragma unroll
        for (int ks = 0; ks < KPAD / 16; ++ks) {
            uint32_t a[4][4], b[4][2], t[4];
            #pragma unroll
            for (int mt = 0; mt < 4; ++mt)
                ldsm4(a[mt], aAddr0 + mt * 16 * 208 + ks * 32);
            #pragma unroll
            for (int np = 0; np < 2; ++np) {
                ldsm4(t, bAddr0 + np * 16 * 208 + ks * 32);
                b[2 * np + 0][0] = t[0]; b[2 * np + 1][0] = t[1];
                b[2 * np + 0][1] = t[2]; b[2 * np + 1][1] = t[3];
            }
            #pragma unroll
            for (int mt = 0; mt < 4; ++mt)
                #pragma unroll
                for (int nt = 0; nt < 4; ++nt)
                    hmma(acc[mt][nt], a[mt], b[nt]);
        }
    }

    // ---- phase 3: epilogue (bias + direct STG into this CTA's 128-col half)
    {
        const float* bs = (const float*)(smem + OFF_BIAS);
        float* outp = out + (size_t)pt * (CCH * NOUT) + hh * NHALF;
        const int r0 = wm * 64 + (lane >> 2);
        const int c0 = wn * 32 + 2 * (lane & 3);
        float2 bv[4];
        #pragma unroll
        for (int nt = 0; nt < 4; ++nt)
            bv[nt] = *(const float2*)(bs + c0 + nt * 8);
        #pragma unroll
        for (int mt = 0; mt < 4; ++mt) {
            const int row = r0 + mt * 16;
            #pragma unroll
            for (int nt = 0; nt < 4; ++nt) {
                const int col = c0 + nt * 8;
                float2 v0, v1;
                v0.x = acc[mt][nt][0] + bv[nt].x;
                v0.y = acc[mt][nt][1] + bv[nt].y;
                v1.x = acc[mt][nt][2] + bv[nt].x;
                v1.y = acc[mt][nt][3] + bv[nt].y;
                *(float2*)(outp + (size_t)row * NOUT + col) = v0;
                *(float2*)(outp + (size_t)(row + 8) * NOUT + col) = v1;
            }
        }
    }
}

// ---------------------------------------------------------------------------
extern "C" void kernel_launch(void* const* d_in, const int* in_sizes, int n_in,
                              void* d_out, int out_size) {
    const float* points = (const float*)d_in[0];
    const float* feat0  = (const float*)d_in[1];
    const float* feat1  = (const float*)d_in[2];
    const float* feat2  = (const float*)d_in[3];
    const float* Wg     = (const float*)d_in[4];
    const float* biasg  = (const float*)d_in[5];
    float* out = (float*)d_out;

    prep_B_kernel<<<(NOUT * STRD + 255) / 256, 256>>>(Wg);

    cudaFuncSetAttribute(mlfs_kernel,
                         cudaFuncAttributeMaxDynamicSharedMemorySize, SMEM_TOTAL);
    mlfs_kernel<<<BSZ * NPTS * 2, 256, SMEM_TOTAL>>>(points, feat0, feat1, feat2,
                                                     biasg, out);
}

// round 5
// speedup vs baseline: 1.3736x; 1.2890x over previous
#include <cuda_runtime.h>
#include <cuda_bf16.h>
#include <cstdint>

// ---------------------------------------------------------------------------
// MultiLevelFeatureSampler on GB300 (sm_103a via base-target sm_103 SASS)
//
// Per point: D[128x256] = P[128x83] @ W^T (+ bias); P = gather of 83 taps.
// fp32 via split-bf16: D = Ah*Bh + Ah*Bl + Al*Bh, HMMA m16n8k16 fp32 accum.
//
// R5: persistent CTAs (grid=148, 1/SM).  B (both split halves) resident in
// smem for the CTA lifetime.  A double-buffered; the gather+convert of point
// p+1 is interleaved into the MMA k-steps of point p, hiding LDG latency
// behind tensor work.  N=256 done as two sequential 128-col sub-GEMMs so the
// accumulator file stays at 64 regs (no spill).
// ---------------------------------------------------------------------------

#define NSM   148
#define NPTS_TOTAL 2048
#define CCH   128
#define DTOT  83
#define GTOT  (CCH * DTOT)     // 10624 gather elements per point
#define STRD  104              // row stride in bf16 (208 B, ldmatrix conflict-free)
#define NOUT  256

#define H0 93
#define W0 305
#define H1 47
#define W1 153
#define H2 24
#define W2 77

// ---- smem layout (bytes) ----
#define OFF_TAPP    0                              // 83 * 8B tap base pointers
#define OFF_TAPS    672                            // 83 * 4B channel strides
#define OFF_BIAS    1008                           // 256 * 4B
#define OFF_A0      2048
#define ABUF        (2 * CCH * STRD * 2)           // Ah+Al = 53248
#define AL_OFF      (CCH * STRD * 2)               // 26624 within a buffer
#define OFF_A1      (OFF_A0 + ABUF)                // 55296
#define OFF_BH      (OFF_A1 + ABUF)                // 108544 (256 x 208B)
#define OFF_BL      (OFF_BH + NOUT * STRD * 2)     // 161792
#define SMEM_TOTAL  (OFF_BL + NOUT * STRD * 2)     // 215040 (~210 KB)

// W split-bf16 scratch, [0]=hi, [1]=lo, row-major 256 x STRD (pads zeroed)
__device__ __align__(16) __nv_bfloat16 g_B[2][NOUT * STRD];

// ---------------------------------------------------------------------------
__device__ __forceinline__ uint32_t smem_u32(const void* p) {
    uint32_t a;
    asm("{ .reg .u64 t; cvta.to.shared.u64 t, %1; cvt.u32.u64 %0, t; }"
        : "=r"(a) : "l"(p));
    return a;
}

__device__ __forceinline__ void cp16(uint32_t dst, const void* src) {
    asm volatile("cp.async.cg.shared.global [%0], [%1], 16;"
                 :: "r"(dst), "l"(src) : "memory");
}

__device__ __forceinline__ void ldsm4(uint32_t* r, uint32_t addr) {
    asm volatile("ldmatrix.sync.aligned.m8n8.x4.shared.b16 {%0,%1,%2,%3}, [%4];"
                 : "=r"(r[0]), "=r"(r[1]), "=r"(r[2]), "=r"(r[3]) : "r"(addr));
}

__device__ __forceinline__ void hmma(float* c, const uint32_t* a, const uint32_t* b) {
    asm volatile(
        "mma.sync.aligned.m16n8k16.row.col.f32.bf16.bf16.f32 "
        "{%0,%1,%2,%3}, {%4,%5,%6,%7}, {%8,%9}, {%0,%1,%2,%3};"
        : "+f"(c[0]), "+f"(c[1]), "+f"(c[2]), "+f"(c[3])
        : "r"(a[0]), "r"(a[1]), "r"(a[2]), "r"(a[3]), "r"(b[0]), "r"(b[1]));
}

// Per-tap gather metadata for point pn (called with d = tid < 83)
__device__ __forceinline__ void compute_taps(char* smem, int d, int pn,
                                             const float* __restrict__ points,
                                             const float* __restrict__ feat0,
                                             const float* __restrict__ feat1,
                                             const float* __restrict__ feat2) {
    const float* f; int H, Wd, ks, dd;
    if (d < 49)      { f = feat0; H = H0; Wd = W0; ks = 7; dd = d; }
    else if (d < 74) { f = feat1; H = H1; Wd = W1; ks = 5; dd = d - 49; }
    else             { f = feat2; H = H2; Wd = W2; ks = 3; dd = d - 74; }
    int half = ks >> 1;
    int jj = dd / ks - half;
    int kk = dd % ks - half;
    int bi = pn >> 9;
    float px = points[pn * 2 + 0];
    float py = points[pn * 2 + 1];
    float x = fminf(fmaxf(px * (float)(Wd - 1), 0.f), (float)(Wd - 1));
    float y = fminf(fmaxf(py * (float)(H  - 1), 0.f), (float)(H  - 1));
    int ox = (int)floorf(fminf(fmaxf(x + (float)kk, 0.f), (float)(Wd - 1)));
    int oy = (int)floorf(fminf(fmaxf(y + (float)jj, 0.f), (float)(H  - 1)));
    *(int*)(smem + OFF_TAPS + d * 4) = H * Wd;
    *(const float**)(smem + OFF_TAPP + d * 8) =
        f + (size_t)bi * CCH * H * Wd + (oy * Wd + ox);
}

// ---------------------------------------------------------------------------
// Prologue: W (256x83 fp32) -> g_B hi/lo bf16, row stride STRD, pads zeroed.
__global__ void prep_B_kernel(const float* __restrict__ Wg) {
    int idx = blockIdx.x * 256 + threadIdx.x;
    if (idx >= NOUT * STRD) return;
    int row = idx / STRD;
    int col = idx - row * STRD;
    float v = (col < DTOT) ? Wg[row * DTOT + col] : 0.f;
    __nv_bfloat16 hi = __float2bfloat16(v);
    __nv_bfloat16 lo = __float2bfloat16(v - __bfloat162float(hi));
    g_B[0][idx] = hi;
    g_B[1][idx] = lo;
}

// ---------------------------------------------------------------------------
__global__ void __launch_bounds__(256, 1)
mlfs_kernel(const float* __restrict__ points,
            const float* __restrict__ feat0,
            const float* __restrict__ feat1,
            const float* __restrict__ feat2,
            const float* __restrict__ biasg,
            float* __restrict__ out) {
    extern __shared__ char smem[];
    const uint32_t smem_base = smem_u32(smem);
    const int tid = threadIdx.x;
    const int wid = tid >> 5;
    const int lane = tid & 31;
    const int r = blockIdx.x;

    // ---- one-time setup: B resident copy (async), bias, A-pad zero ----
    {
        const char* src = (const char*)g_B;
        uint32_t dst = smem_base + OFF_BH;
        const int n16 = (2 * NOUT * STRD * 2) / 16;   // 6656
        #pragma unroll 2
        for (int i = tid; i < n16; i += 256)
            cp16(dst + i * 16, src + (size_t)i * 16);
        asm volatile("cp.async.commit_group;" ::: "memory");
    }
    if (tid < 64)
        ((float4*)(smem + OFF_BIAS))[tid] = ((const float4*)biasg)[tid];

    // zero A pad bytes 160..207 of every row (cols 80..103; gather rewrites
    // 80..82) for both buffers x (Ah, Al): 512 rows total
    {
        float4 z = make_float4(0.f, 0.f, 0.f, 0.f);
        for (int row = tid; row < 512; row += 256) {
            char* base = smem + OFF_A0 + (row >> 7) * AL_OFF + (row & 127) * 208 + 160;
            ((float4*)base)[0] = z; ((float4*)base)[1] = z; ((float4*)base)[2] = z;
        }
    }

    // ---- prologue: taps + full gather for first point into buf 0 ----
    if (tid < DTOT && r < NPTS_TOTAL)
        compute_taps(smem, tid, r, points, feat0, feat1, feat2);
    __syncthreads();

    if (r < NPTS_TOTAL) {
        char* ah = smem + OFF_A0;
        char* al = smem + OFF_A0 + AL_OFF;
        for (int e = tid; e < GTOT; e += 256) {
            int c = e / DTOT;
            int d = e - c * DTOT;
            const float* bp = *(const float* const*)(smem + OFF_TAPP + d * 8);
            int st = *(const int*)(smem + OFF_TAPS + d * 4);
            float v = __ldg(bp + (size_t)c * st);
            __nv_bfloat16 hi = __float2bfloat16(v);
            __nv_bfloat16 lo = __float2bfloat16(v - __bfloat162float(hi));
            int sw = c * 208 + d * 2;
            *(__nv_bfloat16*)(ah + sw) = hi;
            *(__nv_bfloat16*)(al + sw) = lo;
        }
    }
    asm volatile("cp.async.wait_group 0;" ::: "memory");

    // ---- persistent loop over this CTA's points ----
    const int wm = wid >> 2;            // 0..1 (M)
    const int wn = wid & 3;             // 0..3 (N within 128-col half)
    const uint32_t lrow = lane & 15;
    const uint32_t kof2 = ((lane >> 4) << 3) * 2;

    int cur = 0;
    for (int p = r; p < NPTS_TOTAL; p += NSM) {
        const int pn = p + NSM;
        const bool hasnext = (pn < NPTS_TOTAL);

        __syncthreads();   // gather into A[cur] done; taps free to overwrite
        if (tid < DTOT && hasnext)
            compute_taps(smem, tid, pn, points, feat0, feat1, feat2);
        __syncthreads();   // taps + A[cur] visible to all

        const uint32_t aCur = smem_base + OFF_A0 + cur * ABUF;
        char* nbH = smem + OFF_A0 + (cur ^ 1) * ABUF;
        char* nbL = nbH + AL_OFF;
        float* outp = out + (size_t)p * (CCH * NOUT);
        const float* bs = (const float*)(smem + OFF_BIAS);

        #pragma unroll
        for (int hh = 0; hh < 2; ++hh) {
            float acc[4][4][4];
            #pragma unroll
            for (int mt = 0; mt < 4; ++mt)
                #pragma unroll
                for (int nt = 0; nt < 4; ++nt)
                    #pragma unroll
                    for (int q = 0; q < 4; ++q) acc[mt][nt][q] = 0.f;

            #pragma unroll
            for (int pass = 0; pass < 3; ++pass) {
                uint32_t aAddr0 = aCur + ((pass == 2) ? AL_OFF : 0)
                                + (wm * 64 + lrow) * 208 + kof2;
                uint32_t bAddr0 = smem_base + ((pass == 1) ? OFF_BL : OFF_BH)
                                + (hh * 128 + wn * 32 + lrow) * 208 + kof2;
                #pragma unroll
                for (int ks = 0; ks < 6; ++ks) {
                    const int s = hh * 18 + pass * 6 + ks;       // 0..35
                    const int istart = (s < 6) ? 2 * s : s + 6;  // covers i 0..41
                    const int gcnt = (s < 6) ? 2 : 1;

                    // --- gather prefetch for point p+1 (LDG issue) ---
                    float gv[2];
                    int ge[2];
                    bool gok[2];
                    #pragma unroll
                    for (int j = 0; j < 2; ++j) {
                        gok[j] = false;
                        if (j < gcnt) {
                            int e = tid + 256 * (istart + j);
                            if (hasnext && e < GTOT) {
                                int c = e / DTOT;
                                int d = e - c * DTOT;
                                const float* bp =
                                    *(const float* const*)(smem + OFF_TAPP + d * 8);
                                int st = *(const int*)(smem + OFF_TAPS + d * 4);
                                gv[j] = __ldg(bp + (size_t)c * st);
                                ge[j] = e;
                                gok[j] = true;
                            }
                        }
                    }

                    // --- MMA k-step (hides the LDG latency) ---
                    uint32_t a[4][4], b[4][2], t[4];
                    #pragma unroll
                    for (int mt = 0; mt < 4; ++mt)
                        ldsm4(a[mt], aAddr0 + mt * 16 * 208 + ks * 32);
                    #pragma unroll
                    for (int np = 0; np < 2; ++np) {
                        ldsm4(t, bAddr0 + np * 16 * 208 + ks * 32);
                        b[2 * np + 0][0] = t[0]; b[2 * np + 1][0] = t[1];
                        b[2 * np + 0][1] = t[2]; b[2 * np + 1][1] = t[3];
                    }
                    #pragma unroll
                    for (int mt = 0; mt < 4; ++mt)
                        #pragma unroll
                        for (int nt = 0; nt < 4; ++nt)
                            hmma(acc[mt][nt], a[mt], b[nt]);

                    // --- gather commit (split-convert + STS) ---
                    #pragma unroll
                    for (int j = 0; j < 2; ++j) {
                        if (gok[j]) {
                            int e = ge[j];
                            int c = e / DTOT;
                            int d = e - c * DTOT;
                            float v = gv[j];
                            __nv_bfloat16 hi = __float2bfloat16(v);
                            __nv_bfloat16 lo =
                                __float2bfloat16(v - __bfloat162float(hi));
                            int sw = c * 208 + d * 2;
                            *(__nv_bfloat16*)(nbH + sw) = hi;
                            *(__nv_bfloat16*)(nbL + sw) = lo;
                        }
                    }
                }
            }

            // --- epilogue for this 128-col half (regs only) ---
            {
                const int r0 = wm * 64 + (lane >> 2);
                const int c0 = wn * 32 + 2 * (lane & 3);
                float2 bv[4];
                #pragma unroll
                for (int nt = 0; nt < 4; ++nt)
                    bv[nt] = *(const float2*)(bs + hh * 128 + c0 + nt * 8);
                float* oph = outp + hh * 128;
                #pragma unroll
                for (int mt = 0; mt < 4; ++mt) {
                    const int row = r0 + mt * 16;
                    #pragma unroll
                    for (int nt = 0; nt < 4; ++nt) {
                        const int col = c0 + nt * 8;
                        float2 v0, v1;
                        v0.x = acc[mt][nt][0] + bv[nt].x;
                        v0.y = acc[mt][nt][1] + bv[nt].y;
                        v1.x = acc[mt][nt][2] + bv[nt].x;
                        v1.y = acc[mt][nt][3] + bv[nt].y;
                        *(float2*)(oph + (size_t)row * NOUT + col) = v0;
                        *(float2*)(oph + (size_t)(row + 8) * NOUT + col) = v1;
                    }
                }
            }
        }

        cur ^= 1;
    }
}

// ---------------------------------------------------------------------------
extern "C" void kernel_launch(void* const* d_in, const int* in_sizes, int n_in,
                              void* d_out, int out_size) {
    const float* points = (const float*)d_in[0];
    const float* feat0  = (const float*)d_in[1];
    const float* feat1  = (const float*)d_in[2];
    const float* feat2  = (const float*)d_in[3];
    const float* Wg     = (const float*)d_in[4];
    const float* biasg  = (const float*)d_in[5];
    float* out = (float*)d_out;

    prep_B_kernel<<<(NOUT * STRD + 255) / 256, 256>>>(Wg);

    cudaFuncSetAttribute(mlfs_kernel,
                         cudaFuncAttributeMaxDynamicSharedMemorySize, SMEM_TOTAL);
    mlfs_kernel<<<NSM, 256, SMEM_TOTAL>>>(points, feat0, feat1, feat2,
                                          biasg, out);
}